// round 6
// baseline (speedup 1.0000x reference)
#include <cuda_runtime.h>
#include <cstddef>

// KitNET_5257039970983 — R6: 4 rows/thread (dual pair-streams), shared M loads,
// warp-local staging + zero block barriers (from R5), tails via smem.
// Inputs: x(B,100) f32, Wt(10,7,10), hbias_t(10,7), vbias_t(10,10),
//         Wh(7,10), hbias_h(7), vbias_h(10), clusters(10,10) i32
// Output: head_out(B,10) then tails(B,10), fp32.

#define NTILES 10
#define CDIM   10
#define HDIM   7
#define FDIM   100
#define TPB    128
#define RPB    512
#define NPAIRS 256                // pairs per block; pair p <-> rows (base+p, base+p+256)
#define PSTR   11                 // u64 per pair-row (88B, conflict-free LDS/STS.64)
#define SLICE_U64 (64*PSTR)       // 704 u64 = 5632 B per warp (64 pairs)

// ---- smem layout (byte offsets) ----
#define OFF_XS    0               // 4 warps * 5632 = 22528
#define OFF_TLS   22528           // u64[256][10] tails = 20480
#define OFF_MT    43008           // u64[10][10][10] = 8000
#define OFF_BT    51008           // u64[10][10] = 800
#define OFF_MH    51808           // u64[10][10] = 800
#define OFF_BH    52608           // u64[10] = 80
#define OFF_PERM  52688           // int[100] = 400
#define OFF_TBASE 53088           // int[10] = 40
#define SMEM_BYTES 53136

typedef unsigned long long u64;

__device__ __forceinline__ u64 fma2(u64 a, u64 b, u64 c) {
    u64 d;
    asm("fma.rn.f32x2 %0, %1, %2, %3;" : "=l"(d) : "l"(a), "l"(b), "l"(c));
    return d;
}
__device__ __forceinline__ u64 pack2(float x, float y) {
    u64 d;
    asm("mov.b64 %0, {%1, %2};" : "=l"(d) : "f"(x), "f"(y));
    return d;
}
__device__ __forceinline__ void unpack2(u64 a, float& x, float& y) {
    asm("mov.b64 {%0, %1}, %2;" : "=f"(x), "=f"(y) : "l"(a));
}

// ---- warp-local staging for 64 pairs: load into regs ----
__device__ __forceinline__ void stage_load(const float* __restrict__ x, u64 rv[20],
                                           const int* __restrict__ pp, int tb,
                                           int rowbase, int B, int lane)
{
    if (tb >= 0) {
        #pragma unroll
        for (int i = 0; i < 10; ++i) {
            int id = 32*i + lane;                 // 0..319 : (pair, kchunk)
            int p  = id / 5;
            int k  = id - 5*p;
            int r0 = rowbase + p;
            int r1 = r0 + 256;
            const float* g0 = x + (size_t)r0 * FDIM + tb + 2*k;
            float2 v0 = make_float2(0.0f, 0.0f);
            float2 v1 = make_float2(0.0f, 0.0f);
            if (r0 < B) v0 = *(const float2*)g0;
            if (r1 < B) v1 = *(const float2*)(g0 + 256 * FDIM);
            rv[2*i]   = pack2(v0.x, v1.x);
            rv[2*i+1] = pack2(v0.y, v1.y);
        }
    } else {
        #pragma unroll
        for (int i = 0; i < 20; ++i) {
            int id = 32*i + lane;                 // 0..639 : (pair, col)
            int p  = id / 10;
            int j  = id - 10*p;
            int r0 = rowbase + p;
            int r1 = r0 + 256;
            unsigned col = (unsigned)pp[j];
            float v0 = 0.0f, v1 = 0.0f;
            if (r0 < B) v0 = x[(size_t)r0 * FDIM + col];
            if (r1 < B) v1 = x[(size_t)r1 * FDIM + col];
            rv[i] = pack2(v0, v1);
        }
    }
}

__device__ __forceinline__ void stage_store(u64* __restrict__ slf, const u64 rv[20],
                                            int tb, int lane)
{
    if (tb >= 0) {
        #pragma unroll
        for (int i = 0; i < 10; ++i) {
            int id = 32*i + lane;
            int p  = id / 5;
            int k  = id - 5*p;
            slf[p*PSTR + 2*k]     = rv[2*i];
            slf[p*PSTR + 2*k + 1] = rv[2*i+1];
        }
    } else {
        #pragma unroll
        for (int i = 0; i < 20; ++i) {
            int id = 32*i + lane;
            int p  = id / 10;
            int j  = id - 10*p;
            slf[p*PSTR + j] = rv[i];
        }
    }
}

// dual-stream matvec + sum-of-squares: shares every M/b load across 2 streams
__device__ __forceinline__ void dual_sq(const u64 xc0[CDIM], const u64 xc1[CDIM],
                                        const u64* __restrict__ Mt,
                                        const u64* __restrict__ bt,
                                        u64& sq0, u64& sq1)
{
    const ulonglong2* Mv  = (const ulonglong2*)Mt;
    const ulonglong2* btv = (const ulonglong2*)bt;
    u64 s0 = 0ull, s1 = 0ull;
    #pragma unroll
    for (int cp = 0; cp < 5; ++cp) {
        ulonglong2 bb = btv[cp];
        u64 a00 = bb.x, a01 = bb.y;
        u64 a10 = bb.x, a11 = bb.y;
        #pragma unroll
        for (int cc = 0; cc < 5; ++cc) {
            ulonglong2 w0 = Mv[(2*cp)   * 5 + cc];
            ulonglong2 w1 = Mv[(2*cp+1) * 5 + cc];
            a00 = fma2(xc0[2*cc],   w0.x, a00);
            a00 = fma2(xc0[2*cc+1], w0.y, a00);
            a01 = fma2(xc0[2*cc],   w1.x, a01);
            a01 = fma2(xc0[2*cc+1], w1.y, a01);
            a10 = fma2(xc1[2*cc],   w0.x, a10);
            a10 = fma2(xc1[2*cc+1], w0.y, a10);
            a11 = fma2(xc1[2*cc],   w1.x, a11);
            a11 = fma2(xc1[2*cc+1], w1.y, a11);
        }
        s0 = fma2(a00, a00, s0);
        s0 = fma2(a01, a01, s0);
        s1 = fma2(a10, a10, s1);
        s1 = fma2(a11, a11, s1);
    }
    sq0 = s0;
    sq1 = s1;
}

__global__ void __launch_bounds__(TPB, 4) kitnet_kernel(
    const float* __restrict__ x,
    const float* __restrict__ Wt,
    const float* __restrict__ hbt,
    const float* __restrict__ vbt,
    const float* __restrict__ Wh,
    const float* __restrict__ hbh,
    const float* __restrict__ vbh,
    const int*   __restrict__ clusters,
    float* __restrict__ out,
    int B)
{
    extern __shared__ char smem[];
    u64* xs    = (u64*)(smem + OFF_XS);
    u64* stl   = (u64*)(smem + OFF_TLS);
    u64* MT    = (u64*)(smem + OFF_MT);
    u64* BT    = (u64*)(smem + OFF_BT);
    u64* MH    = (u64*)(smem + OFF_MH);
    u64* BH    = (u64*)(smem + OFF_BH);
    int* perm  = (int*)(smem + OFF_PERM);
    int* tbase = (int*)(smem + OFF_TBASE);

    const int tid  = threadIdx.x;
    const int lane = tid & 31;
    const int wid  = tid >> 5;
    const int base = blockIdx.x * RPB;

    // ---- prologue P1: raw weights -> scratch (inside XS region), perm ----
    float* scr = (float*)xs;
    float* sW   = scr;          // [10][7][10]
    float* sHB  = scr + 700;
    float* sVB  = scr + 770;
    float* sWH  = scr + 870;
    float* sHBH = scr + 940;
    float* sVBH = scr + 947;
    for (int i = tid; i < 700; i += TPB) sW[i]  = Wt[i];
    for (int i = tid; i < 70;  i += TPB) sHB[i] = hbt[i];
    for (int i = tid; i < 100; i += TPB) sVB[i] = vbt[i];
    for (int i = tid; i < 70;  i += TPB) sWH[i] = Wh[i];
    if (tid < HDIM)   sHBH[tid] = hbh[tid];
    if (tid < NTILES) sVBH[tid] = vbh[tid];
    for (int i = tid; i < FDIM; i += TPB) perm[i] = clusters[i];
    __syncthreads();

    // ---- prologue P2: fold matrices (M = W^T W - I etc.), fast-path detect ----
    for (int i = tid; i < NTILES * CDIM * CDIM; i += TPB) {
        int t  = i / 100;
        int r  = i - t * 100;
        int co = r / 10;
        int ci = r - co * 10;
        float m = (ci == co) ? -1.0f : 0.0f;
        #pragma unroll
        for (int h = 0; h < HDIM; ++h)
            m += sW[t * 70 + h * 10 + ci] * sW[t * 70 + h * 10 + co];
        ((float2*)MT)[i] = make_float2(m, m);
    }
    for (int i = tid; i < NTILES * CDIM; i += TPB) {
        int t = i / 10, c = i - t * 10;
        float b = sVB[i];
        #pragma unroll
        for (int h = 0; h < HDIM; ++h)
            b += sHB[t * HDIM + h] * sW[t * 70 + h * 10 + c];
        ((float2*)BT)[i] = make_float2(b, b);
    }
    for (int i = tid; i < CDIM * CDIM; i += TPB) {
        int j = i / 10, ii = i - j * 10;
        float m = 0.0f;
        #pragma unroll
        for (int h = 0; h < HDIM; ++h)
            m += sWH[h * 10 + ii] * sWH[h * 10 + j];
        ((float2*)MH)[i] = make_float2(m, m);
    }
    if (tid < NTILES) {
        float b = sVBH[tid];
        #pragma unroll
        for (int h = 0; h < HDIM; ++h)
            b += sHBH[h] * sWH[h * 10 + tid];
        ((float2*)BH)[tid] = make_float2(b, b);
    }
    if (tid < NTILES) {
        const int* pp = perm + tid * 10;
        int b0 = pp[0];
        bool ok = ((b0 & 1) == 0);
        #pragma unroll
        for (int j = 1; j < 10; ++j) ok = ok && (pp[j] == b0 + j);
        tbase[tid] = ok ? b0 : -1;
    }
    __syncthreads();
    // ======== no block barriers beyond this point ========

    const int P       = wid * 64;           // block-local pair base for this warp
    const int rowbase = base + P;
    u64* slf = xs + wid * SLICE_U64;

    u64 rv[20];

    // stage tile 0
    stage_load(x, rv, perm, tbase[0], rowbase, B, lane);
    stage_store(slf, rv, tbase[0], lane);
    __syncwarp();

    #pragma unroll 1
    for (int t = 0; t < NTILES; ++t) {
        if (t < NTILES - 1)
            stage_load(x, rv, perm + (t + 1) * 10, tbase[t + 1], rowbase, B, lane);

        u64 xc0[CDIM], xc1[CDIM];
        const u64* s0 = slf + lane * PSTR;
        const u64* s1 = slf + (32 + lane) * PSTR;
        #pragma unroll
        for (int j = 0; j < CDIM; ++j) { xc0[j] = s0[j]; xc1[j] = s1[j]; }

        u64 sq0, sq1;
        dual_sq(xc0, xc1, MT + t * 100, BT + t * 10, sq0, sq1);

        float e0, e1;
        unpack2(sq0, e0, e1);
        stl[(P + lane) * 10 + t]      = pack2(0.5f * __logf(e0 * 0.1f),
                                              0.5f * __logf(e1 * 0.1f));
        unpack2(sq1, e0, e1);
        stl[(P + 32 + lane) * 10 + t] = pack2(0.5f * __logf(e0 * 0.1f),
                                              0.5f * __logf(e1 * 0.1f));

        __syncwarp();
        if (t < NTILES - 1)
            stage_store(slf, rv, tbase[t + 1], lane);
        __syncwarp();
    }

    // ---- head: head_out = tails @ MH^T + b_h (dual-stream, shared MH loads) ----
    u64 tl0[NTILES], tl1[NTILES];
    {
        const ulonglong2* t0p = (const ulonglong2*)(stl + (P + lane) * 10);
        const ulonglong2* t1p = (const ulonglong2*)(stl + (P + 32 + lane) * 10);
        #pragma unroll
        for (int j = 0; j < 5; ++j) {
            ulonglong2 v0 = t0p[j], v1 = t1p[j];
            tl0[2*j] = v0.x; tl0[2*j+1] = v0.y;
            tl1[2*j] = v1.x; tl1[2*j+1] = v1.y;
        }
    }
    u64 ho0[NTILES], ho1[NTILES];
    {
        const ulonglong2* MHv = (const ulonglong2*)MH;
        const ulonglong2* BHv = (const ulonglong2*)BH;
        #pragma unroll
        for (int jp = 0; jp < 5; ++jp) {
            ulonglong2 bb = BHv[jp];
            u64 a00 = bb.x, a01 = bb.y;
            u64 a10 = bb.x, a11 = bb.y;
            #pragma unroll
            for (int tt = 0; tt < 5; ++tt) {
                ulonglong2 w0 = MHv[(2*jp)   * 5 + tt];
                ulonglong2 w1 = MHv[(2*jp+1) * 5 + tt];
                a00 = fma2(tl0[2*tt],   w0.x, a00);
                a00 = fma2(tl0[2*tt+1], w0.y, a00);
                a01 = fma2(tl0[2*tt],   w1.x, a01);
                a01 = fma2(tl0[2*tt+1], w1.y, a01);
                a10 = fma2(tl1[2*tt],   w0.x, a10);
                a10 = fma2(tl1[2*tt+1], w0.y, a10);
                a11 = fma2(tl1[2*tt],   w1.x, a11);
                a11 = fma2(tl1[2*tt+1], w1.y, a11);
            }
            ho0[2*jp] = a00; ho0[2*jp+1] = a01;
            ho1[2*jp] = a10; ho1[2*jp+1] = a11;
        }
    }

    // ---- warp-local output restage: round 0 = head, round 1 = tails ----
    // slice float view: half0 = floats [0,640) (rows rowbase..+64),
    //                   half1 = floats [640,1280) (rows rowbase+256..+64)
    float* slff = (float*)slf;
    u64*   slfu = (u64*)slf;
    const long long B10 = (long long)B * NTILES;

    #pragma unroll 1
    for (int r = 0; r < 2; ++r) {
        const u64* v0 = r ? tl0 : ho0;
        const u64* v1 = r ? tl1 : ho1;
        #pragma unroll
        for (int n = 0; n < 5; ++n) {
            float a0, b0, a1, b1;
            unpack2(v0[2*n],   a0, b0);
            unpack2(v0[2*n+1], a1, b1);
            slfu[lane * 5 + n]       = pack2(a0, a1);   // half0, pair lane
            slfu[320 + lane * 5 + n] = pack2(b0, b1);   // half1, pair lane
            unpack2(v1[2*n],   a0, b0);
            unpack2(v1[2*n+1], a1, b1);
            slfu[(32 + lane) * 5 + n]       = pack2(a0, a1);
            slfu[320 + (32 + lane) * 5 + n] = pack2(b0, b1);
        }
        __syncwarp();
        const long long bound = (long long)(r + 1) * B10;
        #pragma unroll
        for (int i = 0; i < 10; ++i) {
            int f  = 32 * i + lane;            // float4 index 0..319
            int h  = f / 160;
            int f2 = f - 160 * h;
            long long off = (long long)r * B10
                          + (long long)(rowbase + h * 256) * 10 + 4 * f2;
            float4 q = ((const float4*)slff)[f];
            if (off + 4 <= bound) {
                *(float4*)(out + off) = q;
            } else {
                const float* qf = (const float*)&q;
                #pragma unroll
                for (int kk = 0; kk < 4; ++kk)
                    if (off + kk < bound) out[off + kk] = qf[kk];
            }
        }
        __syncwarp();
    }
}

extern "C" void kernel_launch(void* const* d_in, const int* in_sizes, int n_in,
                              void* d_out, int out_size)
{
    const float* x   = (const float*)d_in[0];
    const float* Wt  = (const float*)d_in[1];
    const float* hbt = (const float*)d_in[2];
    const float* vbt = (const float*)d_in[3];
    const float* Wh  = (const float*)d_in[4];
    const float* hbh = (const float*)d_in[5];
    const float* vbh = (const float*)d_in[6];
    const int*   cls = (const int*)d_in[7];

    const int B = in_sizes[0] / FDIM;
    const int grid = (B + RPB - 1) / RPB;

    cudaFuncSetAttribute(kitnet_kernel, cudaFuncAttributeMaxDynamicSharedMemorySize, SMEM_BYTES);
    kitnet_kernel<<<grid, TPB, SMEM_BYTES>>>(x, Wt, hbt, vbt, Wh, hbh, vbh, cls,
                                             (float*)d_out, B);
}

// round 7
// speedup vs baseline: 2.0088x; 2.0088x over previous
#include <cuda_runtime.h>
#include <cstddef>

// KitNET_5257039970983 — R7: R5 shape (warp-local staging, no block barriers)
// + folded matrices moved to __constant__ memory (off the L1/shared crossbar).
// Setup kernel folds M = W^T W - I etc. once; memcpy-to-symbol; main kernel
// has no prologue at all.
// Output: head_out(B,10) then tails(B,10), fp32.

#define NTILES 10
#define CDIM   10
#define HDIM   7
#define FDIM   100
#define TPB    256
#define RPB    512
#define PSTR   11                 // u64 per pair-row (88B, conflict-free LDS/STS)
#define SLICE_U64 (32*PSTR)       // 352 u64 = 2816 B per warp

typedef unsigned long long u64;

struct FoldData {
    ulonglong2 MT[500];   // [t][co][ci pair]  (m,m)-packed, u64[10][10][10]
    ulonglong2 BT[50];    // [t][co pair]
    ulonglong2 MH[50];    // [j][i pair]
    ulonglong2 BH[5];
    int perm[100];
    int tbase[10];
    int pad[2];
};

__device__   FoldData gF;
__constant__ FoldData cF;

__device__ __forceinline__ u64 fma2(u64 a, u64 b, u64 c) {
    u64 d;
    asm("fma.rn.f32x2 %0, %1, %2, %3;" : "=l"(d) : "l"(a), "l"(b), "l"(c));
    return d;
}
__device__ __forceinline__ u64 pack2(float x, float y) {
    u64 d;
    asm("mov.b64 %0, {%1, %2};" : "=l"(d) : "f"(x), "f"(y));
    return d;
}
__device__ __forceinline__ void unpack2(u64 a, float& x, float& y) {
    asm("mov.b64 {%0, %1}, %2;" : "=f"(x), "=f"(y) : "l"(a));
}

// ================= setup kernel: fold weights into gF (1 block) =================
__global__ void kitnet_setup(const float* __restrict__ Wt,
                             const float* __restrict__ hbt,
                             const float* __restrict__ vbt,
                             const float* __restrict__ Wh,
                             const float* __restrict__ hbh,
                             const float* __restrict__ vbh,
                             const int*   __restrict__ clusters)
{
    __shared__ float sW[700], sHB[70], sVB[100], sWH[70], sHBH[7], sVBH[10];
    const int tid = threadIdx.x;
    for (int i = tid; i < 700; i += TPB) sW[i]  = Wt[i];
    for (int i = tid; i < 70;  i += TPB) sHB[i] = hbt[i];
    for (int i = tid; i < 100; i += TPB) sVB[i] = vbt[i];
    for (int i = tid; i < 70;  i += TPB) sWH[i] = Wh[i];
    if (tid < HDIM)   sHBH[tid] = hbh[tid];
    if (tid < NTILES) sVBH[tid] = vbh[tid];
    __syncthreads();

    float2* MT2 = (float2*)gF.MT;
    float2* BT2 = (float2*)gF.BT;
    float2* MH2 = (float2*)gF.MH;
    float2* BH2 = (float2*)gF.BH;

    for (int i = tid; i < NTILES * CDIM * CDIM; i += TPB) {
        int t  = i / 100;
        int r  = i - t * 100;
        int co = r / 10;
        int ci = r - co * 10;
        float m = (ci == co) ? -1.0f : 0.0f;
        #pragma unroll
        for (int h = 0; h < HDIM; ++h)
            m += sW[t * 70 + h * 10 + ci] * sW[t * 70 + h * 10 + co];
        MT2[i] = make_float2(m, m);
    }
    for (int i = tid; i < NTILES * CDIM; i += TPB) {
        int t = i / 10, c = i - t * 10;
        float b = sVB[i];
        #pragma unroll
        for (int h = 0; h < HDIM; ++h)
            b += sHB[t * HDIM + h] * sW[t * 70 + h * 10 + c];
        BT2[i] = make_float2(b, b);
    }
    for (int i = tid; i < CDIM * CDIM; i += TPB) {
        int j = i / 10, ii = i - j * 10;
        float m = 0.0f;
        #pragma unroll
        for (int h = 0; h < HDIM; ++h)
            m += sWH[h * 10 + ii] * sWH[h * 10 + j];
        MH2[i] = make_float2(m, m);
    }
    if (tid < NTILES) {
        float b = sVBH[tid];
        #pragma unroll
        for (int h = 0; h < HDIM; ++h)
            b += sHBH[h] * sWH[h * 10 + tid];
        BH2[tid] = make_float2(b, b);
    }
    for (int i = tid; i < FDIM; i += TPB) gF.perm[i] = clusters[i];
    if (tid < NTILES) {
        const int* pp = clusters + tid * 10;
        int b0 = pp[0];
        bool ok = ((b0 & 1) == 0);
        #pragma unroll
        for (int j = 1; j < 10; ++j) ok = ok && (pp[j] == b0 + j);
        gF.tbase[tid] = ok ? b0 : -1;
    }
}

// ================= main kernel =================

// warp-local staging: one tile's 10 cols for this warp's 32 pairs -> regs
__device__ __forceinline__ void stage_load(const float* __restrict__ x, float rv[20],
                                           int t, int rowbase, int B, int lane)
{
    const int tb = cF.tbase[t];
    if (tb >= 0) {
        #pragma unroll
        for (int i = 0; i < 10; ++i) {
            int id = 32*i + lane;                  // 0..319
            int p  = id / 10;
            int rem = id - 10*p;
            int h  = rem / 5;
            int k  = rem - 5*h;
            int row = rowbase + p + h*256;
            float2 v = make_float2(0.0f, 0.0f);
            if (row < B) v = *(const float2*)(x + (size_t)row*FDIM + tb + 2*k);
            rv[2*i]   = v.x;
            rv[2*i+1] = v.y;
        }
    } else {
        const int* pp = cF.perm + t * 10;
        #pragma unroll
        for (int i = 0; i < 20; ++i) {
            int id = 32*i + lane;                  // 0..639
            int p  = id / 20;
            int rem = id - 20*p;
            int h  = rem / 10;
            int j  = rem - 10*h;
            int row = rowbase + p + h*256;
            float v = 0.0f;
            if (row < B) v = x[(size_t)row*FDIM + pp[j]];
            rv[i] = v;
        }
    }
}

__device__ __forceinline__ void stage_store(float* __restrict__ slf, const float rv[20],
                                            int t, int lane)
{
    const int tb = cF.tbase[t];
    if (tb >= 0) {
        #pragma unroll
        for (int i = 0; i < 10; ++i) {
            int id = 32*i + lane;
            int p  = id / 10;
            int rem = id - 10*p;
            int h  = rem / 5;
            int k  = rem - 5*h;
            slf[p*22 + 4*k + h]     = rv[2*i];
            slf[p*22 + 4*k + 2 + h] = rv[2*i+1];
        }
    } else {
        #pragma unroll
        for (int i = 0; i < 20; ++i) {
            int id = 32*i + lane;
            int p  = id / 20;
            int rem = id - 20*p;
            int h  = rem / 10;
            int j  = rem - 10*h;
            slf[p*22 + 2*j + h] = rv[i];
        }
    }
}

// err = xc @ M_t + b_t with M/b from constant bank ; packed sum of squares
__device__ __forceinline__ u64 compute_tile(const u64 xc[CDIM], int t)
{
    const int mb = t * 50;
    const int bb0 = t * 5;
    u64 sq = 0ull;
    #pragma unroll
    for (int cp = 0; cp < 5; ++cp) {
        ulonglong2 bb = cF.BT[bb0 + cp];
        u64 a0 = bb.x, a1 = bb.y;
        #pragma unroll
        for (int cc = 0; cc < 5; ++cc) {
            ulonglong2 w0 = cF.MT[mb + (2*cp)   * 5 + cc];
            ulonglong2 w1 = cF.MT[mb + (2*cp+1) * 5 + cc];
            a0 = fma2(xc[2*cc],   w0.x, a0);
            a0 = fma2(xc[2*cc+1], w0.y, a0);
            a1 = fma2(xc[2*cc],   w1.x, a1);
            a1 = fma2(xc[2*cc+1], w1.y, a1);
        }
        sq = fma2(a0, a0, sq);
        sq = fma2(a1, a1, sq);
    }
    return sq;
}

__global__ void __launch_bounds__(TPB, 3) kitnet_main(
    const float* __restrict__ x,
    float* __restrict__ out,
    int B)
{
    __shared__ u64 xs[8 * SLICE_U64];          // 22528 B

    const int tid  = threadIdx.x;
    const int lane = tid & 31;
    const int wid  = tid >> 5;
    const int base = blockIdx.x * RPB;

    const int rowbase = base + wid * 32;
    u64*   xsw = xs + wid * SLICE_U64;
    float* slf = (float*)xsw;

    float rv[20];
    u64 tails[NTILES];

    // stage tile 0
    stage_load(x, rv, 0, rowbase, B, lane);
    stage_store(slf, rv, 0, lane);
    __syncwarp();

    #pragma unroll 1
    for (int t = 0; t < NTILES; ++t) {
        if (t < NTILES - 1)
            stage_load(x, rv, t + 1, rowbase, B, lane);

        u64 xc[CDIM];
        #pragma unroll
        for (int j = 0; j < CDIM; ++j) xc[j] = xsw[lane * PSTR + j];

        u64 sq = compute_tile(xc, t);
        float e0, e1;
        unpack2(sq, e0, e1);
        tails[t] = pack2(0.5f * __logf(e0 * 0.1f), 0.5f * __logf(e1 * 0.1f));

        __syncwarp();                          // all lanes done reading slice
        if (t < NTILES - 1)
            stage_store(slf, rv, t + 1, lane);
        __syncwarp();                          // writes visible for next xc load
    }

    // ---- head: head_out = tails @ MH^T + b_h (constant-bank weights) ----
    u64 ho[NTILES];
    #pragma unroll
    for (int jp = 0; jp < 5; ++jp) {
        ulonglong2 bb = cF.BH[jp];
        u64 a0 = bb.x, a1 = bb.y;
        #pragma unroll
        for (int tt = 0; tt < 5; ++tt) {
            ulonglong2 w0 = cF.MH[(2*jp)   * 5 + tt];
            ulonglong2 w1 = cF.MH[(2*jp+1) * 5 + tt];
            a0 = fma2(tails[2*tt],   w0.x, a0);
            a0 = fma2(tails[2*tt+1], w0.y, a0);
            a1 = fma2(tails[2*tt],   w1.x, a1);
            a1 = fma2(tails[2*tt+1], w1.y, a1);
        }
        ho[2*jp]   = a0;
        ho[2*jp+1] = a1;
    }

    // ---- warp-local output restage: round 0 = head, round 1 = tails ----
    const long long B10 = (long long)B * NTILES;
    #pragma unroll 1
    for (int r = 0; r < 2; ++r) {
        const u64* src = r ? tails : ho;
        #pragma unroll
        for (int n = 0; n < NTILES; ++n) {
            float a, b;
            unpack2(src[n], a, b);
            slf[lane * 10 + n]       = a;      // rows rowbase..+32
            slf[320 + lane * 10 + n] = b;      // rows rowbase+256..+32
        }
        __syncwarp();
        const long long bound = (long long)(r + 1) * B10;
        #pragma unroll
        for (int i = 0; i < 5; ++i) {
            int q  = lane + 32 * i;            // 0..159 float4 index
            int h  = (q >= 80) ? 1 : 0;
            int qq = q - 80 * h;
            long long off = (long long)r * B10
                          + (long long)(rowbase + h * 256) * 10 + 4 * qq;
            float4 v = *(const float4*)(slf + h * 320 + 4 * qq);
            if (off + 4 <= bound) {
                *(float4*)(out + off) = v;
            } else {
                const float* vf = (const float*)&v;
                #pragma unroll
                for (int kk = 0; kk < 4; ++kk)
                    if (off + kk < bound) out[off + kk] = vf[kk];
            }
        }
        __syncwarp();
    }
}

extern "C" void kernel_launch(void* const* d_in, const int* in_sizes, int n_in,
                              void* d_out, int out_size)
{
    const float* x   = (const float*)d_in[0];
    const float* Wt  = (const float*)d_in[1];
    const float* hbt = (const float*)d_in[2];
    const float* vbt = (const float*)d_in[3];
    const float* Wh  = (const float*)d_in[4];
    const float* hbh = (const float*)d_in[5];
    const float* vbh = (const float*)d_in[6];
    const int*   cls = (const int*)d_in[7];

    const int B = in_sizes[0] / FDIM;
    const int grid = (B + RPB - 1) / RPB;

    kitnet_setup<<<1, TPB>>>(Wt, hbt, vbt, Wh, hbh, vbh, cls);

    void* gfp = nullptr;
    cudaGetSymbolAddress(&gfp, gF);
    cudaMemcpyToSymbolAsync(cF, gfp, sizeof(FoldData), 0,
                            cudaMemcpyDeviceToDevice, 0);

    kitnet_main<<<grid, TPB>>>(x, (float*)d_out, B);
}